// round 16
// baseline (speedup 1.0000x reference)
#include <cuda_runtime.h>
#include <cuda_bf16.h>
#include <math.h>

// Problem constants
#define NTOK   8192
#define DIM    256
#define HH     8
#define HD     32
#define WW     64
#define NW     128          // NTOK / WW
#define T6     216          // 3*40 + 3*32
#define QSCALE 0.17677669529663687f   // 32^-0.5

typedef unsigned long long u64;
typedef unsigned int       u32;

// ---- packed f32x2 helpers (sm_100+) ----
__device__ __forceinline__ void ffma2(u64 &c, u64 a, u64 b) {
    asm("fma.rn.f32x2 %0, %1, %2, %0;" : "+l"(c) : "l"(a), "l"(b));
}
__device__ __forceinline__ u64 pk2(float lo, float hi) {
    u64 r; asm("mov.b64 %0, {%1, %2};" : "=l"(r) : "f"(lo), "f"(hi)); return r;
}
__device__ __forceinline__ float2 up2(u64 v) {
    float2 r; asm("mov.b64 {%0, %1}, %2;" : "=f"(r.x), "=f"(r.y) : "l"(v)); return r;
}
__device__ __forceinline__ float hsum2(u64 v) { float2 p = up2(v); return p.x + p.y; }

// Global scratch (static device allocations -- allowed)
__device__ float g_q[NTOK * DIM];
__device__ float g_k[NTOK * DIM];
__device__ float g_v[NTOK * DIM];
__device__ float g_att[NTOK * DIM];

// pre-split bf16 operand buffers (A: 8192 rows; B: up to 768 rows)
__device__ __nv_bfloat16 g_sahi[NTOK * DIM];
__device__ __nv_bfloat16 g_salo[NTOK * DIM];
__device__ __nv_bfloat16 g_sbhi[3 * DIM * DIM];
__device__ __nv_bfloat16 g_sblo[3 * DIM * DIM];

// ---------------------------------------------------------------------------
// split kernel: fp32 -> (hi,lo) bf16.
// which: 0 = src->A buf, 1 = src->B buf, 2 = g_att->A buf, 3 = src->B buf.
// ---------------------------------------------------------------------------
__global__ __launch_bounds__(256) void split_kernel(
    const float* __restrict__ src, int which, int n4)
{
    __nv_bfloat16 *hi, *lo;
    if (which == 0)      { hi = g_sahi; lo = g_salo; }
    else if (which == 1) { hi = g_sbhi; lo = g_sblo; }
    else if (which == 2) { hi = g_sahi; lo = g_salo; src = g_att; }
    else                 { hi = g_sbhi; lo = g_sblo; }

    int i = blockIdx.x * 256 + threadIdx.x;
    if (i >= n4) return;
    float4 v = ((const float4*)src)[i];
    __nv_bfloat16 h0 = __float2bfloat16(v.x);
    __nv_bfloat16 h1 = __float2bfloat16(v.y);
    __nv_bfloat16 h2 = __float2bfloat16(v.z);
    __nv_bfloat16 h3 = __float2bfloat16(v.w);
    __nv_bfloat162* hp = (__nv_bfloat162*)hi;
    __nv_bfloat162* lp = (__nv_bfloat162*)lo;
    hp[2 * i]     = __halves2bfloat162(h0, h1);
    hp[2 * i + 1] = __halves2bfloat162(h2, h3);
    lp[2 * i]     = __halves2bfloat162(
        __float2bfloat16(v.x - __bfloat162float(h0)),
        __float2bfloat16(v.y - __bfloat162float(h1)));
    lp[2 * i + 1] = __halves2bfloat162(
        __float2bfloat16(v.z - __bfloat162float(h2)),
        __float2bfloat16(v.w - __bfloat162float(h3)));
}

// ---------------------------------------------------------------------------
// mma.sync helpers (sm_80+ baseline PTX; works on sm_103 non-a)
// ---------------------------------------------------------------------------
__device__ __forceinline__ u32 smem_u32(const void* p) {
    u32 a;
    asm("{ .reg .u64 t; cvta.to.shared.u64 t, %1; cvt.u32.u64 %0, t; }"
        : "=r"(a) : "l"(p));
    return a;
}
__device__ __forceinline__ void ldsm4(u32* r, u32 addr) {
    asm volatile("ldmatrix.sync.aligned.m8n8.x4.shared.b16 {%0,%1,%2,%3}, [%4];"
                 : "=r"(r[0]), "=r"(r[1]), "=r"(r[2]), "=r"(r[3]) : "r"(addr));
}
__device__ __forceinline__ void ldsm2(u32* r, u32 addr) {
    asm volatile("ldmatrix.sync.aligned.m8n8.x2.shared.b16 {%0,%1}, [%2];"
                 : "=r"(r[0]), "=r"(r[1]) : "r"(addr));
}
__device__ __forceinline__ void mma_bf16(float* d, const u32* a, const u32* b) {
    asm volatile(
        "mma.sync.aligned.m16n8k16.row.col.f32.bf16.bf16.f32 "
        "{%0,%1,%2,%3}, {%4,%5,%6,%7}, {%8,%9}, {%0,%1,%2,%3};"
        : "+f"(d[0]), "+f"(d[1]), "+f"(d[2]), "+f"(d[3])
        : "r"(a[0]), "r"(a[1]), "r"(a[2]), "r"(a[3]), "r"(b[0]), "r"(b[1]));
}

// ---------------------------------------------------------------------------
// Split-bf16 tensor-core GEMM over pre-split buffers:
// C[M,N] = A[M,256] @ B[N,256]^T (+bias); D = Ah*Bh + Ah*Bl + Al*Bh.
// Per-CTA tile 128x128, BK=32, 256 threads (8 warps 2Mx4N; warp tile 64x32).
// mode 0: qkv epilogue (route q/k/v + scale q). mode 1: plain out + bias.
// ---------------------------------------------------------------------------
#define SROW 40   // bf16 row stride (80B): ldmatrix conflict-free

__global__ __launch_bounds__(256) void mma_gemm_kernel(
    const float* __restrict__ bias, float* __restrict__ outp, int mode)
{
    __shared__ __align__(16) __nv_bfloat16 sAhi[128 * SROW];
    __shared__ __align__(16) __nv_bfloat16 sAlo[128 * SROW];
    __shared__ __align__(16) __nv_bfloat16 sBhi[128 * SROW];
    __shared__ __align__(16) __nv_bfloat16 sBlo[128 * SROW];

    const int tid = threadIdx.x, wid = tid >> 5, lane = tid & 31;
    const int m0 = blockIdx.x * 128, n0 = blockIdx.y * 128;
    const int warpM = wid & 1, warpN = wid >> 1;   // 2 x 4 warp grid

    const u32 aHiB = smem_u32(sAhi), aLoB = smem_u32(sAlo);
    const u32 bHiB = smem_u32(sBhi), bLoB = smem_u32(sBlo);

    float acc[4][4][4];
#pragma unroll
    for (int mt = 0; mt < 4; mt++)
#pragma unroll
        for (int nt = 0; nt < 4; nt++)
#pragma unroll
            for (int f = 0; f < 4; f++) acc[mt][nt][f] = 0.f;

    // per-lane ldmatrix bases
    const u32 aRow = (u32)(warpM * 64 + (lane & 15));
    const u32 aColByte = (u32)((lane >> 4) * 16);
    const u32 bRowLane = (u32)(lane & 7);
    const u32 bColByte = (u32)(((lane >> 3) & 1) * 16);

    // copy indices: 512 uint4 per buffer, 2 per thread
    const int r0 = tid >> 2, q0 = tid & 3;          // e = tid
    const int r1 = (tid + 256) >> 2, q1 = tid & 3;  // e = tid + 256

    for (int kc = 0; kc < 8; kc++) {
        __syncthreads();
        {
            const int kb = kc * 32;
            *(uint4*)(sAhi + r0 * SROW + q0 * 8) =
                *(const uint4*)(g_sahi + (size_t)(m0 + r0) * 256 + kb + q0 * 8);
            *(uint4*)(sAhi + r1 * SROW + q1 * 8) =
                *(const uint4*)(g_sahi + (size_t)(m0 + r1) * 256 + kb + q1 * 8);
            *(uint4*)(sAlo + r0 * SROW + q0 * 8) =
                *(const uint4*)(g_salo + (size_t)(m0 + r0) * 256 + kb + q0 * 8);
            *(uint4*)(sAlo + r1 * SROW + q1 * 8) =
                *(const uint4*)(g_salo + (size_t)(m0 + r1) * 256 + kb + q1 * 8);
            *(uint4*)(sBhi + r0 * SROW + q0 * 8) =
                *(const uint4*)(g_sbhi + (size_t)(n0 + r0) * 256 + kb + q0 * 8);
            *(uint4*)(sBhi + r1 * SROW + q1 * 8) =
                *(const uint4*)(g_sbhi + (size_t)(n0 + r1) * 256 + kb + q1 * 8);
            *(uint4*)(sBlo + r0 * SROW + q0 * 8) =
                *(const uint4*)(g_sblo + (size_t)(n0 + r0) * 256 + kb + q0 * 8);
            *(uint4*)(sBlo + r1 * SROW + q1 * 8) =
                *(const uint4*)(g_sblo + (size_t)(n0 + r1) * 256 + kb + q1 * 8);
        }
        __syncthreads();

#pragma unroll
        for (int s = 0; s < 2; s++) {
            const u32 sb = (u32)(s * 32);
            u32 ahi[4][4], alo[4][4], bhi[4][2], blo[4][2];
#pragma unroll
            for (int mt = 0; mt < 4; mt++) {
                u32 off = (aRow + mt * 16) * (SROW * 2) + sb + aColByte;
                ldsm4(ahi[mt], aHiB + off);
                ldsm4(alo[mt], aLoB + off);
            }
#pragma unroll
            for (int nt = 0; nt < 4; nt++) {
                u32 off = (u32)(warpN * 32 + nt * 8 + bRowLane) * (SROW * 2)
                          + sb + bColByte;
                ldsm2(bhi[nt], bHiB + off);
                ldsm2(blo[nt], bLoB + off);
            }
#pragma unroll
            for (int mt = 0; mt < 4; mt++)
#pragma unroll
                for (int nt = 0; nt < 4; nt++) {
                    mma_bf16(acc[mt][nt], ahi[mt], bhi[nt]);
                    mma_bf16(acc[mt][nt], ahi[mt], blo[nt]);
                    mma_bf16(acc[mt][nt], alo[mt], bhi[nt]);
                }
        }
    }

    // ---- epilogue ----
    const int mBase = m0 + warpM * 64 + (lane >> 2);
    const int nBase = n0 + warpN * 32 + (lane & 3) * 2;
    if (mode == 0) {
        const int s = nBase >> 8;                 // warp's 32 cols never cross
        float* dst = (s == 0) ? g_q : (s == 1) ? g_k : g_v;
        const float sc = (s == 0) ? QSCALE : 1.0f;
#pragma unroll
        for (int mt = 0; mt < 4; mt++)
#pragma unroll
            for (int nt = 0; nt < 4; nt++) {
                int n = nBase + nt * 8, col = n & 255;
                float b0 = bias[n], b1 = bias[n + 1];
                int mA = mBase + mt * 16, mB = mA + 8;
                float2 oA = {(acc[mt][nt][0] + b0) * sc,
                             (acc[mt][nt][1] + b1) * sc};
                float2 oB = {(acc[mt][nt][2] + b0) * sc,
                             (acc[mt][nt][3] + b1) * sc};
                *(float2*)&dst[(size_t)mA * 256 + col] = oA;
                *(float2*)&dst[(size_t)mB * 256 + col] = oB;
            }
    } else {
#pragma unroll
        for (int mt = 0; mt < 4; mt++)
#pragma unroll
            for (int nt = 0; nt < 4; nt++) {
                int n = nBase + nt * 8;
                float b0 = bias[n], b1 = bias[n + 1];
                int mA = mBase + mt * 16, mB = mA + 8;
                float2 oA = {acc[mt][nt][0] + b0, acc[mt][nt][1] + b1};
                float2 oB = {acc[mt][nt][2] + b0, acc[mt][nt][3] + b1};
                *(float2*)&outp[(size_t)mA * 256 + n] = oA;
                *(float2*)&outp[(size_t)mB * 256 + n] = oB;
            }
    }
}

// ---------------------------------------------------------------------------
// Attention kernel: EXACT R7 version (best measured, 512 threads).
// ---------------------------------------------------------------------------
#define SM_FLOATS 53024
#define SMEM_BYTES (SM_FLOATS * 4)

__global__ __launch_bounds__(512) void attn_kernel(
    const float* __restrict__ n_coords,
    const float* __restrict__ qx, const float* __restrict__ kx,
    const float* __restrict__ vx,
    const float* __restrict__ qr, const float* __restrict__ kr,
    const float* __restrict__ vr)
{
    extern __shared__ __align__(16) float sm[];
    float* scw   = sm;
    float* sq    = sm + 384;     // stride 33
    float* sk    = sm + 2496;    // stride 33
    float* svT   = sm + 4608;    // stride 65
    float* stabQ = sm + 6688;
    float* stabK = sm + 13600;
    float* sdq   = sm + 20512;   // stride 220
    float* sdk   = sm + 34592;   // stride 220
    float* slogT = sm + 48672;   // stride 68, [j][i]
    float* satT  = sm + 20512;   // stride 68, [t][i]   (aliases sdq after logits)
    float* vtabT = sm + 35200;   // stride 217, [d][t]  (aliases sdk tail)
    u64*   s_idx = (u64*)(sm + 6688);   // u64[4096] over stabQ/K (after Dq/Dk)

    const int nb = blockIdx.x, h = blockIdx.y;
    const int tid = threadIdx.x;
    const int l = tid & 31, w = tid >> 5;
    const int tok0 = nb * WW;

    for (int s = tid; s < WW * 6; s += 512) {
        int i = s / 6, c = s % 6;
        scw[s] = n_coords[(tok0 + i) * 6 + c] * (c < 3 ? 4.0f : 8.0f);
    }
    for (int s = tid; s < WW * HD; s += 512) {
        int i = s >> 5, d = s & 31;
        int g = (tok0 + i) * 256 + h * 32 + d;
        sq[i * 33 + d]  = g_q[g];
        sk[i * 33 + d]  = g_k[g];
        svT[d * 65 + i] = g_v[g];
    }
    for (int s = tid; s < T6 * HD; s += 512) {
        int t = s >> 5, d = s & 31;
        stabQ[s] = (t < 120) ? qx[(t * 8 + h) * 32 + d]
                             : qr[((t - 120) * 8 + h) * 32 + d];
        stabK[s] = (t < 120) ? kx[(t * 8 + h) * 32 + d]
                             : kr[((t - 120) * 8 + h) * 32 + d];
    }
    __syncthreads();

    {
        const int i = tid & 63, grp = tid >> 6;
        const int t0 = grp * 27, t1 = t0 + 27;
        u64 a2[16];
#pragma unroll
        for (int d2 = 0; d2 < 16; d2++)
            a2[d2] = pk2(sq[i * 33 + 2 * d2], sq[i * 33 + 2 * d2 + 1]);
        for (int t = t0; t < t1; t++) {
            const ulonglong2* tv = (const ulonglong2*)(stabQ + t * 32);
            u64 acc = pk2(0.f, 0.f);
#pragma unroll
            for (int d4 = 0; d4 < 8; d4++) {
                ulonglong2 tvv = tv[d4];
                ffma2(acc, a2[2 * d4],     tvv.x);
                ffma2(acc, a2[2 * d4 + 1], tvv.y);
            }
            sdq[i * 220 + t] = hsum2(acc);
        }
#pragma unroll
        for (int d2 = 0; d2 < 16; d2++)
            a2[d2] = pk2(sk[i * 33 + 2 * d2], sk[i * 33 + 2 * d2 + 1]);
        for (int t = t0; t < t1; t++) {
            const ulonglong2* tv = (const ulonglong2*)(stabK + t * 32);
            u64 acc = pk2(0.f, 0.f);
#pragma unroll
            for (int d4 = 0; d4 < 8; d4++) {
                ulonglong2 tvv = tv[d4];
                ffma2(acc, a2[2 * d4],     tvv.x);
                ffma2(acc, a2[2 * d4 + 1], tvv.y);
            }
            sdk[i * 220 + t] = hsum2(acc);
        }
    }
    __syncthreads();

    {
        const int basec[6] = {0, 40, 80, 120, 152, 184};
        const int offc[6]  = {20, 20, 20, 16, 16, 16};
        const int hic[6]   = {39, 39, 39, 31, 31, 31};
#pragma unroll
        for (int r = 0; r < 4; r++) {
            int i = w * 4 + r;
            float ci[6];
#pragma unroll
            for (int c = 0; c < 6; c++) ci[c] = scw[i * 6 + c];
            u64 q2[16];
#pragma unroll
            for (int d2 = 0; d2 < 16; d2++)
                q2[d2] = pk2(sq[i * 33 + 2 * d2], sq[i * 33 + 2 * d2 + 1]);
#pragma unroll
            for (int jj = 0; jj < 2; jj++) {
                int j = l + jj * 32;
                const float* krow = sk + j * 33;
                u64 acc2 = pk2(0.f, 0.f);
#pragma unroll
                for (int d2 = 0; d2 < 16; d2++)
                    ffma2(acc2, q2[d2], pk2(krow[2 * d2], krow[2 * d2 + 1]));
                float acc = hsum2(acc2);
                u64 pack = 0;
#pragma unroll
                for (int c = 0; c < 6; c++) {
                    int id = (int)floorf(ci[c] - scw[j * 6 + c]) + offc[c];
                    id = min(max(id, 0), hic[c]);
                    int t = basec[c] + id;
                    acc += sdq[i * 220 + t] + sdk[j * 220 + t];
                    pack |= (u64)t << (8 * c);
                }
                slogT[j * 68 + i] = acc;
                s_idx[i * 64 + j] = pack;
            }
        }
    }
    __syncthreads();

    for (int s = tid; s < T6 * 68; s += 512) satT[s] = 0.f;
    for (int s = tid; s < T6 * HD; s += 512) {
        int t = s >> 5, d = s & 31;
        float val = (t < 120) ? vx[(t * 8 + h) * 32 + d]
                              : vr[((t - 120) * 8 + h) * 32 + d];
        vtabT[d * 217 + t] = val;
    }
    __syncthreads();

#pragma unroll
    for (int r = 0; r < 4; r++) {
        int i = w * 4 + r;
        float v0 = slogT[l * 68 + i], v1 = slogT[(l + 32) * 68 + i];
        float m = fmaxf(v0, v1);
#pragma unroll
        for (int o = 16; o > 0; o >>= 1)
            m = fmaxf(m, __shfl_xor_sync(0xffffffffu, m, o));
        float e0 = __expf(v0 - m), e1 = __expf(v1 - m);
        float s = e0 + e1;
#pragma unroll
        for (int o = 16; o > 0; o >>= 1)
            s += __shfl_xor_sync(0xffffffffu, s, o);
        float inv = 1.0f / s;
        slogT[l * 68 + i]        = e0 * inv;
        slogT[(l + 32) * 68 + i] = e1 * inv;
    }
    __syncwarp();

    if (l < 24) {
        int r = l / 6, c = l % 6;
        int i = w * 4 + r;
        const u64* ip = s_idx + i * 64;
        const int sh = 8 * c;
        for (int j = 0; j < 64; j++) {
            int t = (int)((ip[j] >> sh) & 255u);
            satT[t * 68 + i] += slogT[j * 68 + i];
        }
    }
    __syncwarp();

    {
        const int i0 = w * 4;
        u64 acc01 = pk2(0.f, 0.f), acc23 = pk2(0.f, 0.f);
        const float* svrow = svT + l * 65;
#pragma unroll 8
        for (int j = 0; j < 64; j++) {
            float4 a4 = *(const float4*)&slogT[j * 68 + i0];
            float v = svrow[j];
            u64 vd = pk2(v, v);
            ffma2(acc01, pk2(a4.x, a4.y), vd);
            ffma2(acc23, pk2(a4.z, a4.w), vd);
        }
        const float* vtrow = vtabT + l * 217;
#pragma unroll 8
        for (int t = 0; t < T6; t++) {
            float4 a4 = *(const float4*)&satT[t * 68 + i0];
            float v = vtrow[t];
            u64 vd = pk2(v, v);
            ffma2(acc01, pk2(a4.x, a4.y), vd);
            ffma2(acc23, pk2(a4.z, a4.w), vd);
        }
        float2 o01 = up2(acc01), o23 = up2(acc23);
        const int ob = (tok0 + i0) * 256 + h * 32 + l;
        g_att[ob]       = o01.x;
        g_att[ob + 256] = o01.y;
        g_att[ob + 512] = o23.x;
        g_att[ob + 768] = o23.y;
    }
}

// ---------------------------------------------------------------------------
extern "C" void kernel_launch(void* const* d_in, const int* in_sizes, int n_in,
                              void* d_out, int out_size)
{
    const float* feats    = (const float*)d_in[0];
    const float* n_coords = (const float*)d_in[1];
    const float* qkv_w    = (const float*)d_in[2];
    const float* qkv_b    = (const float*)d_in[3];
    const float* qx       = (const float*)d_in[4];
    const float* kx       = (const float*)d_in[5];
    const float* vx       = (const float*)d_in[6];
    const float* qr       = (const float*)d_in[7];
    const float* kr       = (const float*)d_in[8];
    const float* vr       = (const float*)d_in[9];
    const float* pw       = (const float*)d_in[10];
    const float* pb       = (const float*)d_in[11];
    float* out = (float*)d_out;

    cudaFuncSetAttribute(attn_kernel,
                         cudaFuncAttributeMaxDynamicSharedMemorySize,
                         SMEM_BYTES);

    // split feats + qkv_w, then qkv GEMM on tensor cores
    split_kernel<<<2048, 256>>>(feats, 0, NTOK * DIM / 4);
    split_kernel<<<192, 256>>>(qkv_w, 1, 3 * DIM * DIM / 4);
    mma_gemm_kernel<<<dim3(64, 6), 256>>>(qkv_b, nullptr, 0);

    attn_kernel<<<dim3(NW, HH), 512, SMEM_BYTES>>>(n_coords, qx, kx, vx,
                                                   qr, kr, vr);

    // split g_att + proj_w, then proj GEMM
    split_kernel<<<2048, 256>>>(nullptr, 2, NTOK * DIM / 4);
    split_kernel<<<64, 256>>>(pw, 3, DIM * DIM / 4);
    mma_gemm_kernel<<<dim3(64, 2), 256>>>(pb, out, 1);
}

// round 17
// speedup vs baseline: 1.0710x; 1.0710x over previous
#include <cuda_runtime.h>
#include <cuda_bf16.h>
#include <math.h>

// Problem constants
#define NTOK   8192
#define DIM    256
#define HH     8
#define HD     32
#define WW     64
#define NW     128          // NTOK / WW
#define T6     216          // 3*40 + 3*32
#define QSCALE 0.17677669529663687f   // 32^-0.5

typedef unsigned long long u64;
typedef unsigned int       u32;

// ---- packed f32x2 helpers (sm_100+) ----
__device__ __forceinline__ void ffma2(u64 &c, u64 a, u64 b) {
    asm("fma.rn.f32x2 %0, %1, %2, %0;" : "+l"(c) : "l"(a), "l"(b));
}
__device__ __forceinline__ u64 pk2(float lo, float hi) {
    u64 r; asm("mov.b64 %0, {%1, %2};" : "=l"(r) : "f"(lo), "f"(hi)); return r;
}
__device__ __forceinline__ float2 up2(u64 v) {
    float2 r; asm("mov.b64 {%0, %1}, %2;" : "=f"(r.x), "=f"(r.y) : "l"(v)); return r;
}
__device__ __forceinline__ float hsum2(u64 v) { float2 p = up2(v); return p.x + p.y; }

// Global scratch (static device allocations -- allowed)
__device__ float g_q[NTOK * DIM];
__device__ float g_k[NTOK * DIM];
__device__ float g_v[NTOK * DIM];
__device__ float g_att[NTOK * DIM];

// ---------------------------------------------------------------------------
// mma.sync helpers (sm_80+ baseline PTX; works on sm_103 non-a)
// ---------------------------------------------------------------------------
__device__ __forceinline__ u32 smem_u32(const void* p) {
    u32 a;
    asm("{ .reg .u64 t; cvta.to.shared.u64 t, %1; cvt.u32.u64 %0, t; }"
        : "=r"(a) : "l"(p));
    return a;
}
__device__ __forceinline__ void ldsm4(u32* r, u32 addr) {
    asm volatile("ldmatrix.sync.aligned.m8n8.x4.shared.b16 {%0,%1,%2,%3}, [%4];"
                 : "=r"(r[0]), "=r"(r[1]), "=r"(r[2]), "=r"(r[3]) : "r"(addr));
}
__device__ __forceinline__ void ldsm2(u32* r, u32 addr) {
    asm volatile("ldmatrix.sync.aligned.m8n8.x2.shared.b16 {%0,%1}, [%2];"
                 : "=r"(r[0]), "=r"(r[1]) : "r"(addr));
}
__device__ __forceinline__ void mma_bf16(float* d, const u32* a, const u32* b) {
    asm volatile(
        "mma.sync.aligned.m16n8k16.row.col.f32.bf16.bf16.f32 "
        "{%0,%1,%2,%3}, {%4,%5,%6,%7}, {%8,%9}, {%0,%1,%2,%3};"
        : "+f"(d[0]), "+f"(d[1]), "+f"(d[2]), "+f"(d[3])
        : "r"(a[0]), "r"(a[1]), "r"(a[2]), "r"(a[3]), "r"(b[0]), "r"(b[1]));
}

// ---------------------------------------------------------------------------
// Split-bf16 tensor-core GEMM: C[M,N] = A[M,256] @ B[N,256]^T (+bias).
// Per-CTA tile 128x64, BK=32, 256 threads (8 warps: 2M x 4N, warp tile 64x16).
// In-kernel fp32 -> (hi,lo) bf16 conversion with REGISTER PREFETCH of the
// next chunk overlapped against the mma block. D = Ah*Bh + Ah*Bl + Al*Bh.
// mode 0: A = Ain (feats), qkv epilogue. mode 1: A = g_att, plain out + bias.
// ---------------------------------------------------------------------------
#define SROW 40   // bf16 row stride (80B): ldmatrix conflict-free

__global__ __launch_bounds__(256) void mma_gemm_kernel(
    const float* __restrict__ Ain, const float* __restrict__ B,
    const float* __restrict__ bias, float* __restrict__ outp, int mode)
{
    __shared__ __align__(16) __nv_bfloat16 sAhi[128 * SROW];
    __shared__ __align__(16) __nv_bfloat16 sAlo[128 * SROW];
    __shared__ __align__(16) __nv_bfloat16 sBhi[64 * SROW];
    __shared__ __align__(16) __nv_bfloat16 sBlo[64 * SROW];

    const float* A = (mode == 1) ? g_att : Ain;   // device-symbol resolution

    const int tid = threadIdx.x, wid = tid >> 5, lane = tid & 31;
    const int m0 = blockIdx.x * 128, n0 = blockIdx.y * 64;
    const int warpM = wid & 1, warpN = wid >> 1;   // 2 x 4 warp grid

    const u32 aHiB = smem_u32(sAhi), aLoB = smem_u32(sAlo);
    const u32 bHiB = smem_u32(sBhi), bLoB = smem_u32(sBlo);

    float acc[4][2][4];
#pragma unroll
    for (int mt = 0; mt < 4; mt++)
#pragma unroll
        for (int nt = 0; nt < 2; nt++)
#pragma unroll
            for (int f = 0; f < 4; f++) acc[mt][nt][f] = 0.f;

    const u32 aRow = (u32)(warpM * 64 + (lane & 15));
    const u32 aColByte = (u32)((lane >> 4) * 16);
    const u32 bRowLane = (u32)(lane & 7);
    const u32 bColByte = (u32)(((lane >> 3) & 1) * 16);

    // ---- register prefetch buffers ----
    float4 pa[4], pb[2];
#pragma unroll
    for (int it = 0; it < 4; it++) {
        int e = tid + it * 256;
        pa[it] = *(const float4*)(A + (size_t)(m0 + (e >> 3)) * 256 + (e & 7) * 4);
    }
#pragma unroll
    for (int it = 0; it < 2; it++) {
        int e = tid + it * 256;
        pb[it] = *(const float4*)(B + (size_t)(n0 + (e >> 3)) * 256 + (e & 7) * 4);
    }

    for (int kc = 0; kc < 8; kc++) {
        if (kc > 0) __syncthreads();    // prior mma done reading smem
        // ---- convert held regs -> hi/lo bf16 smem ----
#pragma unroll
        for (int it = 0; it < 4; it++) {
            int e = tid + it * 256;
            int row = e >> 3, c4 = e & 7;
            float4 v = pa[it];
            __nv_bfloat16 h0 = __float2bfloat16(v.x);
            __nv_bfloat16 h1 = __float2bfloat16(v.y);
            __nv_bfloat16 h2 = __float2bfloat16(v.z);
            __nv_bfloat16 h3 = __float2bfloat16(v.w);
            __nv_bfloat162* hp = (__nv_bfloat162*)(sAhi + row * SROW + c4 * 4);
            hp[0] = __halves2bfloat162(h0, h1);
            hp[1] = __halves2bfloat162(h2, h3);
            __nv_bfloat162* lp = (__nv_bfloat162*)(sAlo + row * SROW + c4 * 4);
            lp[0] = __halves2bfloat162(
                __float2bfloat16(v.x - __bfloat162float(h0)),
                __float2bfloat16(v.y - __bfloat162float(h1)));
            lp[1] = __halves2bfloat162(
                __float2bfloat16(v.z - __bfloat162float(h2)),
                __float2bfloat16(v.w - __bfloat162float(h3)));
        }
#pragma unroll
        for (int it = 0; it < 2; it++) {
            int e = tid + it * 256;
            int row = e >> 3, c4 = e & 7;
            float4 v = pb[it];
            __nv_bfloat16 h0 = __float2bfloat16(v.x);
            __nv_bfloat16 h1 = __float2bfloat16(v.y);
            __nv_bfloat16 h2 = __float2bfloat16(v.z);
            __nv_bfloat16 h3 = __float2bfloat16(v.w);
            __nv_bfloat162* hp = (__nv_bfloat162*)(sBhi + row * SROW + c4 * 4);
            hp[0] = __halves2bfloat162(h0, h1);
            hp[1] = __halves2bfloat162(h2, h3);
            __nv_bfloat162* lp = (__nv_bfloat162*)(sBlo + row * SROW + c4 * 4);
            lp[0] = __halves2bfloat162(
                __float2bfloat16(v.x - __bfloat162float(h0)),
                __float2bfloat16(v.y - __bfloat162float(h1)));
            lp[1] = __halves2bfloat162(
                __float2bfloat16(v.z - __bfloat162float(h2)),
                __float2bfloat16(v.w - __bfloat162float(h3)));
        }
        __syncthreads();

        // ---- issue next-chunk loads (overlap with mma below) ----
        if (kc < 7) {
            const int kb = (kc + 1) * 32;
#pragma unroll
            for (int it = 0; it < 4; it++) {
                int e = tid + it * 256;
                pa[it] = *(const float4*)(A + (size_t)(m0 + (e >> 3)) * 256
                                          + kb + (e & 7) * 4);
            }
#pragma unroll
            for (int it = 0; it < 2; it++) {
                int e = tid + it * 256;
                pb[it] = *(const float4*)(B + (size_t)(n0 + (e >> 3)) * 256
                                          + kb + (e & 7) * 4);
            }
        }

        // ---- 2 k16 steps of mma ----
#pragma unroll
        for (int s = 0; s < 2; s++) {
            u32 ahi[4][4], alo[4][4], bhi[2][2], blo[2][2];
            const u32 sb = (u32)(s * 32);
#pragma unroll
            for (int mt = 0; mt < 4; mt++) {
                u32 off = (aRow + mt * 16) * (SROW * 2) + sb + aColByte;
                ldsm4(ahi[mt], aHiB + off);
                ldsm4(alo[mt], aLoB + off);
            }
#pragma unroll
            for (int nt = 0; nt < 2; nt++) {
                u32 off = (u32)(warpN * 16 + nt * 8 + bRowLane) * (SROW * 2)
                          + sb + bColByte;
                ldsm2(bhi[nt], bHiB + off);
                ldsm2(blo[nt], bLoB + off);
            }
#pragma unroll
            for (int mt = 0; mt < 4; mt++)
#pragma unroll
                for (int nt = 0; nt < 2; nt++) {
                    mma_bf16(acc[mt][nt], ahi[mt], bhi[nt]);
                    mma_bf16(acc[mt][nt], ahi[mt], blo[nt]);
                    mma_bf16(acc[mt][nt], alo[mt], bhi[nt]);
                }
        }
    }

    // ---- epilogue ----
    const int mBase = m0 + warpM * 64 + (lane >> 2);
    const int nBase = n0 + warpN * 16 + (lane & 3) * 2;
    if (mode == 0) {
        const int s = nBase >> 8;
        float* dst = (s == 0) ? g_q : (s == 1) ? g_k : g_v;
        const float sc = (s == 0) ? QSCALE : 1.0f;
#pragma unroll
        for (int mt = 0; mt < 4; mt++)
#pragma unroll
            for (int nt = 0; nt < 2; nt++) {
                int n = nBase + nt * 8, col = n & 255;
                float b0 = bias[n], b1 = bias[n + 1];
                int mA = mBase + mt * 16, mB = mA + 8;
                float2 oA = {(acc[mt][nt][0] + b0) * sc,
                             (acc[mt][nt][1] + b1) * sc};
                float2 oB = {(acc[mt][nt][2] + b0) * sc,
                             (acc[mt][nt][3] + b1) * sc};
                *(float2*)&dst[(size_t)mA * 256 + col] = oA;
                *(float2*)&dst[(size_t)mB * 256 + col] = oB;
            }
    } else {
#pragma unroll
        for (int mt = 0; mt < 4; mt++)
#pragma unroll
            for (int nt = 0; nt < 2; nt++) {
                int n = nBase + nt * 8;
                float b0 = bias[n], b1 = bias[n + 1];
                int mA = mBase + mt * 16, mB = mA + 8;
                float2 oA = {acc[mt][nt][0] + b0, acc[mt][nt][1] + b1};
                float2 oB = {acc[mt][nt][2] + b0, acc[mt][nt][3] + b1};
                *(float2*)&outp[(size_t)mA * 256 + n] = oA;
                *(float2*)&outp[(size_t)mB * 256 + n] = oB;
            }
    }
}

// ---------------------------------------------------------------------------
// Attention kernel: R7 structure; ONLY change = v-table read from global
// (coalesced (t*8+h)*32+l, L2-hot) instead of a smem copy.
// ---------------------------------------------------------------------------
#define SM_FLOATS 53024
#define SMEM_BYTES (SM_FLOATS * 4)

__global__ __launch_bounds__(512) void attn_kernel(
    const float* __restrict__ n_coords,
    const float* __restrict__ qx, const float* __restrict__ kx,
    const float* __restrict__ vx,
    const float* __restrict__ qr, const float* __restrict__ kr,
    const float* __restrict__ vr)
{
    extern __shared__ __align__(16) float sm[];
    float* scw   = sm;
    float* sq    = sm + 384;     // stride 33
    float* sk    = sm + 2496;    // stride 33
    float* svT   = sm + 4608;    // stride 65
    float* stabQ = sm + 6688;
    float* stabK = sm + 13600;
    float* sdq   = sm + 20512;   // stride 220
    float* sdk   = sm + 34592;   // stride 220
    float* slogT = sm + 48672;   // stride 68, [j][i]
    float* satT  = sm + 20512;   // stride 68, [t][i]   (aliases sdq after logits)
    u64*   s_idx = (u64*)(sm + 6688);   // u64[4096] over stabQ/K (after Dq/Dk)

    const int nb = blockIdx.x, h = blockIdx.y;
    const int tid = threadIdx.x;
    const int l = tid & 31, w = tid >> 5;
    const int tok0 = nb * WW;

    for (int s = tid; s < WW * 6; s += 512) {
        int i = s / 6, c = s % 6;
        scw[s] = n_coords[(tok0 + i) * 6 + c] * (c < 3 ? 4.0f : 8.0f);
    }
    for (int s = tid; s < WW * HD; s += 512) {
        int i = s >> 5, d = s & 31;
        int g = (tok0 + i) * 256 + h * 32 + d;
        sq[i * 33 + d]  = g_q[g];
        sk[i * 33 + d]  = g_k[g];
        svT[d * 65 + i] = g_v[g];
    }
    for (int s = tid; s < T6 * HD; s += 512) {
        int t = s >> 5, d = s & 31;
        stabQ[s] = (t < 120) ? qx[(t * 8 + h) * 32 + d]
                             : qr[((t - 120) * 8 + h) * 32 + d];
        stabK[s] = (t < 120) ? kx[(t * 8 + h) * 32 + d]
                             : kr[((t - 120) * 8 + h) * 32 + d];
    }
    __syncthreads();

    {
        const int i = tid & 63, grp = tid >> 6;
        const int t0 = grp * 27, t1 = t0 + 27;
        u64 a2[16];
#pragma unroll
        for (int d2 = 0; d2 < 16; d2++)
            a2[d2] = pk2(sq[i * 33 + 2 * d2], sq[i * 33 + 2 * d2 + 1]);
        for (int t = t0; t < t1; t++) {
            const ulonglong2* tv = (const ulonglong2*)(stabQ + t * 32);
            u64 acc = pk2(0.f, 0.f);
#pragma unroll
            for (int d4 = 0; d4 < 8; d4++) {
                ulonglong2 tvv = tv[d4];
                ffma2(acc, a2[2 * d4],     tvv.x);
                ffma2(acc, a2[2 * d4 + 1], tvv.y);
            }
            sdq[i * 220 + t] = hsum2(acc);
        }
#pragma unroll
        for (int d2 = 0; d2 < 16; d2++)
            a2[d2] = pk2(sk[i * 33 + 2 * d2], sk[i * 33 + 2 * d2 + 1]);
        for (int t = t0; t < t1; t++) {
            const ulonglong2* tv = (const ulonglong2*)(stabK + t * 32);
            u64 acc = pk2(0.f, 0.f);
#pragma unroll
            for (int d4 = 0; d4 < 8; d4++) {
                ulonglong2 tvv = tv[d4];
                ffma2(acc, a2[2 * d4],     tvv.x);
                ffma2(acc, a2[2 * d4 + 1], tvv.y);
            }
            sdk[i * 220 + t] = hsum2(acc);
        }
    }
    __syncthreads();

    {
        const int basec[6] = {0, 40, 80, 120, 152, 184};
        const int offc[6]  = {20, 20, 20, 16, 16, 16};
        const int hic[6]   = {39, 39, 39, 31, 31, 31};
#pragma unroll
        for (int r = 0; r < 4; r++) {
            int i = w * 4 + r;
            float ci[6];
#pragma unroll
            for (int c = 0; c < 6; c++) ci[c] = scw[i * 6 + c];
            u64 q2[16];
#pragma unroll
            for (int d2 = 0; d2 < 16; d2++)
                q2[d2] = pk2(sq[i * 33 + 2 * d2], sq[i * 33 + 2 * d2 + 1]);
#pragma unroll
            for (int jj = 0; jj < 2; jj++) {
                int j = l + jj * 32;
                const float* krow = sk + j * 33;
                u64 acc2 = pk2(0.f, 0.f);
#pragma unroll
                for (int d2 = 0; d2 < 16; d2++)
                    ffma2(acc2, q2[d2], pk2(krow[2 * d2], krow[2 * d2 + 1]));
                float acc = hsum2(acc2);
                u64 pack = 0;
#pragma unroll
                for (int c = 0; c < 6; c++) {
                    int id = (int)floorf(ci[c] - scw[j * 6 + c]) + offc[c];
                    id = min(max(id, 0), hic[c]);
                    int t = basec[c] + id;
                    acc += sdq[i * 220 + t] + sdk[j * 220 + t];
                    pack |= (u64)t << (8 * c);
                }
                slogT[j * 68 + i] = acc;
                s_idx[i * 64 + j] = pack;
            }
        }
    }
    __syncthreads();

    for (int s = tid; s < T6 * 68; s += 512) satT[s] = 0.f;
    __syncthreads();

#pragma unroll
    for (int r = 0; r < 4; r++) {
        int i = w * 4 + r;
        float v0 = slogT[l * 68 + i], v1 = slogT[(l + 32) * 68 + i];
        float m = fmaxf(v0, v1);
#pragma unroll
        for (int o = 16; o > 0; o >>= 1)
            m = fmaxf(m, __shfl_xor_sync(0xffffffffu, m, o));
        float e0 = __expf(v0 - m), e1 = __expf(v1 - m);
        float s = e0 + e1;
#pragma unroll
        for (int o = 16; o > 0; o >>= 1)
            s += __shfl_xor_sync(0xffffffffu, s, o);
        float inv = 1.0f / s;
        slogT[l * 68 + i]        = e0 * inv;
        slogT[(l + 32) * 68 + i] = e1 * inv;
    }
    __syncwarp();

    if (l < 24) {
        int r = l / 6, c = l % 6;
        int i = w * 4 + r;
        const u64* ip = s_idx + i * 64;
        const int sh = 8 * c;
        for (int j = 0; j < 64; j++) {
            int t = (int)((ip[j] >> sh) & 255u);
            satT[t * 68 + i] += slogT[j * 68 + i];
        }
    }
    __syncwarp();

    // ---- out[i][d] = attn @ v + at @ vtab ; vtab from GLOBAL (coalesced) ----
    {
        const int i0 = w * 4;
        u64 acc01 = pk2(0.f, 0.f), acc23 = pk2(0.f, 0.f);
        const float* svrow = svT + l * 65;
#pragma unroll 8
        for (int j = 0; j < 64; j++) {
            float4 a4 = *(const float4*)&slogT[j * 68 + i0];
            float v = svrow[j];
            u64 vd = pk2(v, v);
            ffma2(acc01, pk2(a4.x, a4.y), vd);
            ffma2(acc23, pk2(a4.z, a4.w), vd);
        }
        const float* vxrow = vx + h * 32 + l;   // + t*256
        const float* vrrow = vr + h * 32 + l;
#pragma unroll 8
        for (int t = 0; t < 120; t++) {
            float v = vxrow[(size_t)t * 256];
            float4 a4 = *(const float4*)&satT[t * 68 + i0];
            u64 vd = pk2(v, v);
            ffma2(acc01, pk2(a4.x, a4.y), vd);
            ffma2(acc23, pk2(a4.z, a4.w), vd);
        }
#pragma unroll 8
        for (int t = 0; t < 96; t++) {
            float v = vrrow[(size_t)t * 256];
            float4 a4 = *(const float4*)&satT[(120 + t) * 68 + i0];
            u64 vd = pk2(v, v);
            ffma2(acc01, pk2(a4.x, a4.y), vd);
            ffma2(acc23, pk2(a4.z, a4.w), vd);
        }
        float2 o01 = up2(acc01), o23 = up2(acc23);
        const int ob = (tok0 + i0) * 256 + h * 32 + l;
        g_att[ob]       = o01.x;
        g_att[ob + 256] = o01.y;
        g_att[ob + 512] = o23.x;
        g_att[ob + 768] = o23.y;
    }
}

// ---------------------------------------------------------------------------
extern "C" void kernel_launch(void* const* d_in, const int* in_sizes, int n_in,
                              void* d_out, int out_size)
{
    const float* feats    = (const float*)d_in[0];
    const float* n_coords = (const float*)d_in[1];
    const float* qkv_w    = (const float*)d_in[2];
    const float* qkv_b    = (const float*)d_in[3];
    const float* qx       = (const float*)d_in[4];
    const float* kx       = (const float*)d_in[5];
    const float* vx       = (const float*)d_in[6];
    const float* qr       = (const float*)d_in[7];
    const float* kr       = (const float*)d_in[8];
    const float* vr       = (const float*)d_in[9];
    const float* pw       = (const float*)d_in[10];
    const float* pb       = (const float*)d_in[11];
    float* out = (float*)d_out;

    cudaFuncSetAttribute(attn_kernel,
                         cudaFuncAttributeMaxDynamicSharedMemorySize,
                         SMEM_BYTES);

    // qkv: [8192,768] = feats @ qkv_w^T  (mma.sync split-bf16, prefetched)
    mma_gemm_kernel<<<dim3(64, 12), 256>>>(feats, qkv_w, qkv_b, nullptr, 0);

    attn_kernel<<<dim3(NW, HH), 512, SMEM_BYTES>>>(n_coords, qx, kx, vx,
                                                   qr, kr, vr);

    // proj: [8192,256] = g_att @ proj_w^T  (A resolved to g_att in-kernel)
    mma_gemm_kernel<<<dim3(64, 4), 256>>>(nullptr, pw, pb, out, 1);
}